// round 4
// baseline (speedup 1.0000x reference)
#include <cuda_runtime.h>
#include <math.h>

// ---------------- problem constants ----------------
#define B_  8
#define T_  256
#define MEL_ 128
#define D_  192
#define NC_ 20
#define D2_ 384
#define NT_ 32     // theta updates  (chunk 8)
#define ND_ 4      // delta updates  (chunk 64)
#define EPS_ 1e-5f

typedef unsigned long long u64;

// ---------------- scratch ----------------
__device__ float g_xp [B_*T_*D_];
__device__ float g_x1 [B_*T_*D_];
__device__ float g_x2 [B_*T_*D_];
__device__ float g_h  [B_*T_*D_];
__device__ float g_g2 [B_*T_*D_];
__device__ float g_x3 [B_*T_*D_];
__device__ float g_y  [B_*T_*D_];
__device__ float g_Kd [B_*ND_*D_];
__device__ float g_Vd [B_*ND_*D_];
__device__ float g_Qd [B_*ND_*D_];   // Wq_d-projected keys (tilde)
__device__ float g_Ed [B_*ND_*D_];
__device__ float g_Kt [B_*NT_*D_];
__device__ float g_Vt [B_*NT_*D_];
__device__ float g_Qt [B_*NT_*D_];   // Wq_t-projected keys (tilde)
__device__ float g_Et [B_*NT_*D_];
__device__ float g_Wao [D_*D_];
__device__ float g_bao [D_];
__device__ float g_Wkqd[D_*D_];
__device__ float g_Wkqt[D_*D_];

// coefficient c_d = LR*(a^{d+1}-e^{d+1})/(a-e), a=0.99, e=0.9   (fp32, parallel-safe)
__device__ __forceinline__ float cdv(int d) {
    const float L2A = -0.014499569695115089f;   // log2(0.99)
    const float L2E = -0.152003093445049970f;   // log2(0.90)
    float n = (float)(d + 1);
    return (exp2f(n * L2A) - exp2f(n * L2E)) * (0.1f / 0.09f);
}

// ---------------- f32x2 helpers ----------------
__device__ __forceinline__ u64 ffma2(u64 a, u64 b, u64 c) {
    u64 d; asm("fma.rn.f32x2 %0, %1, %2, %3;" : "=l"(d) : "l"(a), "l"(b), "l"(c)); return d;
}
__device__ __forceinline__ u64 dup2(float b) {
    u64 d; asm("mov.b64 %0, {%1, %1};" : "=l"(d) : "f"(b)); return d;
}
__device__ __forceinline__ float2 unpk(u64 v) {
    float2 r; asm("mov.b64 {%0, %1}, %2;" : "=f"(r.x), "=f"(r.y) : "l"(v)); return r;
}

// ---------------- tiled GEMM (f32x2): C[M,N] = (res?) + A[M,K] @ W[K,N] (+ bias) ----------------
#define BM 64
#define BN 64
#define BK 16
__global__ void __launch_bounds__(256) gemm_tiled(
    float* __restrict__ C, const float* __restrict__ A, const float* __restrict__ W,
    const float* __restrict__ bias, const float* __restrict__ res, int M, int N, int K)
{
    __shared__ float As[BK][BM + 4];   // row = 272B (16B multiple)
    __shared__ float Ws[BK][BN];
    int n0 = blockIdx.x * BN, m0 = blockIdx.y * BM;
    int tid = threadIdx.x;
    int tx = tid & 15, ty = tid >> 4;
    u64 cc[2][4] = {};                 // rows (ty*4+2ip, +1) x cols tx*4+j
    for (int k0 = 0; k0 < K; k0 += BK) {
        {
            int arow = tid >> 2, acol = (tid & 3) * 4;
            float4 v = *(const float4*)&A[(size_t)(m0 + arow) * K + k0 + acol];
            As[acol + 0][arow] = v.x; As[acol + 1][arow] = v.y;
            As[acol + 2][arow] = v.z; As[acol + 3][arow] = v.w;
        }
        {
            int wrow = tid >> 4, wcol = (tid & 15) * 4;
            float4 v = *(const float4*)&W[(size_t)(k0 + wrow) * N + n0 + wcol];
            *(float4*)&Ws[wrow][wcol] = v;
        }
        __syncthreads();
#pragma unroll
        for (int kk = 0; kk < BK; kk++) {
            const u64* pa = (const u64*)&As[kk][ty * 4];
            u64 a01 = pa[0], a23 = pa[1];
            float4 bf = *(const float4*)&Ws[kk][tx * 4];
            u64 b0 = dup2(bf.x), b1 = dup2(bf.y), b2 = dup2(bf.z), b3 = dup2(bf.w);
            cc[0][0] = ffma2(a01, b0, cc[0][0]); cc[0][1] = ffma2(a01, b1, cc[0][1]);
            cc[0][2] = ffma2(a01, b2, cc[0][2]); cc[0][3] = ffma2(a01, b3, cc[0][3]);
            cc[1][0] = ffma2(a23, b0, cc[1][0]); cc[1][1] = ffma2(a23, b1, cc[1][1]);
            cc[1][2] = ffma2(a23, b2, cc[1][2]); cc[1][3] = ffma2(a23, b3, cc[1][3]);
        }
        __syncthreads();
    }
    float c4[4][4];
#pragma unroll
    for (int j = 0; j < 4; j++) {
        float2 v0 = unpk(cc[0][j]), v1 = unpk(cc[1][j]);
        c4[0][j] = v0.x; c4[1][j] = v0.y; c4[2][j] = v1.x; c4[3][j] = v1.y;
    }
#pragma unroll
    for (int i = 0; i < 4; i++) {
        int row = m0 + ty * 4 + i, col = n0 + tx * 4;
        float4 o; float* po = &o.x;
#pragma unroll
        for (int j = 0; j < 4; j++) {
            float v = c4[i][j];
            if (bias) v += bias[col + j];
            if (res)  v += res[(size_t)row * N + col + j];
            po[j] = v;
        }
        *(float4*)&C[(size_t)row * N + col] = o;
    }
}

// ---------------- GEMM (N=384, f32x2) with fused GLU+dw+BN+SiLU epilogue -> out [M,192] ----------------
__global__ void __launch_bounds__(256) gemm_glu(
    float* __restrict__ out, const float* __restrict__ A, const float* __restrict__ W,
    const float* __restrict__ bias,
    const float* __restrict__ dw, const float* __restrict__ db,
    const float* __restrict__ bs, const float* __restrict__ bb, int M, int K)
{
    __shared__ float As[BK][BM + 4];
    __shared__ float Wsa[BK][BN];
    __shared__ float Wsg[BK][BN];
    int n0 = blockIdx.x * BN, m0 = blockIdx.y * BM;
    int tid = threadIdx.x;
    int tx = tid & 15, ty = tid >> 4;
    u64 cA[2][4] = {}, cG[2][4] = {};
    for (int k0 = 0; k0 < K; k0 += BK) {
        {
            int arow = tid >> 2, acol = (tid & 3) * 4;
            float4 v = *(const float4*)&A[(size_t)(m0 + arow) * K + k0 + acol];
            As[acol + 0][arow] = v.x; As[acol + 1][arow] = v.y;
            As[acol + 2][arow] = v.z; As[acol + 3][arow] = v.w;
        }
        {
            int wrow = tid >> 4, wcol = (tid & 15) * 4;
            float4 va = *(const float4*)&W[(size_t)(k0 + wrow) * D2_ + n0 + wcol];
            float4 vg = *(const float4*)&W[(size_t)(k0 + wrow) * D2_ + D_ + n0 + wcol];
            *(float4*)&Wsa[wrow][wcol] = va;
            *(float4*)&Wsg[wrow][wcol] = vg;
        }
        __syncthreads();
#pragma unroll
        for (int kk = 0; kk < BK; kk++) {
            const u64* pa = (const u64*)&As[kk][ty * 4];
            u64 a01 = pa[0], a23 = pa[1];
            float4 ba = *(const float4*)&Wsa[kk][tx * 4];
            float4 bg = *(const float4*)&Wsg[kk][tx * 4];
            u64 p0 = dup2(ba.x), p1 = dup2(ba.y), p2 = dup2(ba.z), p3 = dup2(ba.w);
            u64 q0 = dup2(bg.x), q1 = dup2(bg.y), q2 = dup2(bg.z), q3 = dup2(bg.w);
            cA[0][0] = ffma2(a01, p0, cA[0][0]); cA[0][1] = ffma2(a01, p1, cA[0][1]);
            cA[0][2] = ffma2(a01, p2, cA[0][2]); cA[0][3] = ffma2(a01, p3, cA[0][3]);
            cA[1][0] = ffma2(a23, p0, cA[1][0]); cA[1][1] = ffma2(a23, p1, cA[1][1]);
            cA[1][2] = ffma2(a23, p2, cA[1][2]); cA[1][3] = ffma2(a23, p3, cA[1][3]);
            cG[0][0] = ffma2(a01, q0, cG[0][0]); cG[0][1] = ffma2(a01, q1, cG[0][1]);
            cG[0][2] = ffma2(a01, q2, cG[0][2]); cG[0][3] = ffma2(a01, q3, cG[0][3]);
            cG[1][0] = ffma2(a23, q0, cG[1][0]); cG[1][1] = ffma2(a23, q1, cG[1][1]);
            cG[1][2] = ffma2(a23, q2, cG[1][2]); cG[1][3] = ffma2(a23, q3, cG[1][3]);
        }
        __syncthreads();
    }
    float a4[4][4], g4[4][4];
#pragma unroll
    for (int j = 0; j < 4; j++) {
        float2 v0 = unpk(cA[0][j]), v1 = unpk(cA[1][j]);
        a4[0][j] = v0.x; a4[1][j] = v0.y; a4[2][j] = v1.x; a4[3][j] = v1.y;
        float2 w0 = unpk(cG[0][j]), w1 = unpk(cG[1][j]);
        g4[0][j] = w0.x; g4[1][j] = w0.y; g4[2][j] = w1.x; g4[3][j] = w1.y;
    }
#pragma unroll
    for (int i = 0; i < 4; i++) {
        int row = m0 + ty * 4 + i, col = n0 + tx * 4;
        float4 o; float* po = &o.x;
#pragma unroll
        for (int j = 0; j < 4; j++) {
            float a = a4[i][j] + bias[col + j];
            float g = g4[i][j] + bias[D_ + col + j];
            float h = a * (1.f / (1.f + expf(-g)));
            h = h * dw[col + j] + db[col + j];
            h = h * bs[col + j] + bb[col + j];
            h = h * (1.f / (1.f + expf(-h)));
            po[j] = h;
        }
        *(float4*)&out[(size_t)row * D_ + col] = o;
    }
}

// ---------------- weight prep (one launch):
//   z=0: Wao = Wv_a @ Wo_a (+ bao block),  z=1: Wkqd = Wk_d @ Wq_d^T,  z=2: Wkqt = Wk_t @ Wq_t^T
__global__ void __launch_bounds__(256) prep_kernel(
    float* __restrict__ Wao, float* __restrict__ bao,
    float* __restrict__ Wkqd, float* __restrict__ Wkqt,
    const float* __restrict__ Wv_a, const float* __restrict__ Wo_a,
    const float* __restrict__ bv_a, const float* __restrict__ bo_a,
    const float* __restrict__ Wk_d, const float* __restrict__ Wq_d,
    const float* __restrict__ Wk_t, const float* __restrict__ Wq_t)
{
    int z = blockIdx.z;
    if (blockIdx.y == 3) {
        if (z == 0 && blockIdx.x == 0) {
            int n = threadIdx.x;
            if (n < D_) {
                float s = bo_a[n];
#pragma unroll 8
                for (int e = 0; e < D_; e++) s = fmaf(bv_a[e], Wo_a[e * D_ + n], s);
                bao[n] = s;
            }
        }
        return;
    }
    const float* Am = (z == 0) ? Wv_a : (z == 1) ? Wk_d : Wk_t;
    const float* Bm = (z == 0) ? Wo_a : (z == 1) ? Wq_d : Wq_t;
    float* Cm = (z == 0) ? Wao : (z == 1) ? Wkqd : Wkqt;
    bool transB = (z != 0);

    __shared__ float As[BK][BM + 4];
    __shared__ float Ws[BK][BN];
    int n0 = blockIdx.x * BN, m0 = blockIdx.y * BM;
    int tid = threadIdx.x;
    int tx = tid & 15, ty = tid >> 4;
    u64 cc[2][4] = {};
    for (int k0 = 0; k0 < D_; k0 += BK) {
        {
            int arow = tid >> 2, acol = (tid & 3) * 4;
            float4 v = *(const float4*)&Am[(size_t)(m0 + arow) * D_ + k0 + acol];
            As[acol + 0][arow] = v.x; As[acol + 1][arow] = v.y;
            As[acol + 2][arow] = v.z; As[acol + 3][arow] = v.w;
        }
        {
            int wrow = tid >> 4, wcol = (tid & 15) * 4;
            if (transB) {
#pragma unroll
                for (int u = 0; u < 4; u++)
                    Ws[wrow][wcol + u] = Bm[(size_t)(n0 + wcol + u) * D_ + k0 + wrow];
            } else {
                float4 v = *(const float4*)&Bm[(size_t)(k0 + wrow) * D_ + n0 + wcol];
                *(float4*)&Ws[wrow][wcol] = v;
            }
        }
        __syncthreads();
#pragma unroll
        for (int kk = 0; kk < BK; kk++) {
            const u64* pa = (const u64*)&As[kk][ty * 4];
            u64 a01 = pa[0], a23 = pa[1];
            float4 bf = *(const float4*)&Ws[kk][tx * 4];
            u64 b0 = dup2(bf.x), b1 = dup2(bf.y), b2 = dup2(bf.z), b3 = dup2(bf.w);
            cc[0][0] = ffma2(a01, b0, cc[0][0]); cc[0][1] = ffma2(a01, b1, cc[0][1]);
            cc[0][2] = ffma2(a01, b2, cc[0][2]); cc[0][3] = ffma2(a01, b3, cc[0][3]);
            cc[1][0] = ffma2(a23, b0, cc[1][0]); cc[1][1] = ffma2(a23, b1, cc[1][1]);
            cc[1][2] = ffma2(a23, b2, cc[1][2]); cc[1][3] = ffma2(a23, b3, cc[1][3]);
        }
        __syncthreads();
    }
#pragma unroll
    for (int j = 0; j < 4; j++) {
        float2 v0 = unpk(cc[0][j]), v1 = unpk(cc[1][j]);
        Cm[(size_t)(m0 + ty * 4 + 0) * D_ + n0 + tx * 4 + j] = v0.x;
        Cm[(size_t)(m0 + ty * 4 + 1) * D_ + n0 + tx * 4 + j] = v0.y;
        Cm[(size_t)(m0 + ty * 4 + 2) * D_ + n0 + tx * 4 + j] = v1.x;
        Cm[(size_t)(m0 + ty * 4 + 3) * D_ + n0 + tx * 4 + j] = v1.y;
    }
}

// ---------------- fused K+V+Ktilde gathered projection ----------------
__global__ void __launch_bounds__(192) projKVQ(
    float* __restrict__ Ko, float* __restrict__ Vo, float* __restrict__ Qo,
    const float* __restrict__ A,
    const float* __restrict__ Wk, const float* __restrict__ Wv, const float* __restrict__ Wkq,
    int nUpd, int chunk)
{
    __shared__ float sa[D_];
    int row = blockIdx.x;                 // b*nUpd + i
    int b = row / nUpd, i = row % nUpd;
    int nn = threadIdx.x;
    sa[nn] = A[(size_t)(b * T_ + i * chunk) * D_ + nn];
    __syncthreads();
    float sk = 0.f, sv = 0.f, sq = 0.f;
#pragma unroll 8
    for (int kk = 0; kk < D_; kk++) {
        float a = sa[kk];
        sk = fmaf(a, Wk[kk * D_ + nn], sk);
        sv = fmaf(a, Wv[kk * D_ + nn], sv);
        sq = fmaf(a, Wkq[kk * D_ + nn], sq);
    }
    Ko[(size_t)row * D_ + nn] = sk;
    Vo[(size_t)row * D_ + nn] = sv;
    Qo[(size_t)row * D_ + nn] = sq;
}

// ---------------- err recurrence ----------------
template<int N>
__global__ void __launch_bounds__(256) rec_kernel(
    float* __restrict__ ERR, const float* __restrict__ Kmat, const float* __restrict__ Vmat)
{
    __shared__ float sK[N][D_ + 1];       // stride 193 -> conflict-free row-parallel reads
    __shared__ float sV[N][D_];
    __shared__ float Acf[N][N];
    __shared__ float cdS[N];
    int b = blockIdx.x, tid = threadIdx.x;
    if (tid < N) cdS[tid] = cdv(tid);
    for (int idx = tid; idx < N * D_; idx += 256) {
        int r = idx / D_, c = idx % D_;
        sK[r][c] = Kmat[(size_t)(b * N + r) * D_ + c];
        sV[r][c] = Vmat[(size_t)(b * N + r) * D_ + c];
    }
    __syncthreads();
    const int NP = N * (N - 1) / 2;
    for (int p = tid; p < NP; p += 256) {
        int i = (int)((1.0f + sqrtf(1.0f + 8.0f * (float)p)) * 0.5f);
        while (i * (i - 1) / 2 > p) i--;
        while ((i + 1) * i / 2 <= p) i++;
        int j = p - i * (i - 1) / 2;
        float s0 = 0.f, s1 = 0.f;
#pragma unroll 8
        for (int kk = 0; kk < D_; kk += 2) {
            s0 = fmaf(sK[j][kk],     sK[i][kk],     s0);
            s1 = fmaf(sK[j][kk + 1], sK[i][kk + 1], s1);
        }
        Acf[j][i] = cdS[i - 1 - j] * (s0 + s1);
    }
    __syncthreads();
    if (tid < D_) {
        int e = tid;
        float err[N];
#pragma unroll
        for (int i = 0; i < N; i++) {
            float a0 = 0.f, a1 = 0.f;
#pragma unroll
            for (int j = 0; j < i; j++) {
                if (j & 1) a1 = fmaf(Acf[j][i], err[j], a1);
                else       a0 = fmaf(Acf[j][i], err[j], a0);
            }
            err[i] = sV[i][e] - a0 - a1;
            ERR[(size_t)(b * N + i) * D_ + e] = err[i];
        }
    }
}

// ---------------- fused delta QK (via Ktilde) + x1 = xp + 0.5*retrieval ----------------
__global__ void __launch_bounds__(192) qkx1_kernel(
    float* __restrict__ x1, const float* __restrict__ xp,
    const float* __restrict__ Ktil, const float* __restrict__ Ed)
{
    __shared__ float sK[ND_][D_];
    __shared__ float sE[ND_][D_];
    __shared__ float red[ND_][6];
    __shared__ float alpha[ND_];
    int bt = blockIdx.x;
    int b = bt / T_, t = bt % T_, r = t >> 6;
    int e = threadIdx.x;
#pragma unroll
    for (int j = 0; j < ND_; j++) {
        sK[j][e] = Ktil[(size_t)(b * ND_ + j) * D_ + e];
        sE[j][e] = Ed[(size_t)(b * ND_ + j) * D_ + e];
    }
    __syncthreads();
    float q = xp[(size_t)bt * D_ + e];
    float p[ND_];
#pragma unroll
    for (int j = 0; j < ND_; j++) p[j] = q * sK[j][e];
#pragma unroll
    for (int o = 16; o > 0; o >>= 1)
#pragma unroll
        for (int j = 0; j < ND_; j++) p[j] += __shfl_xor_sync(~0u, p[j], o);
    int w = e >> 5, l = e & 31;
    if (l == 0)
#pragma unroll
        for (int j = 0; j < ND_; j++) red[j][w] = p[j];
    __syncthreads();
    if (e < ND_) {
        float s = 0.f;
#pragma unroll
        for (int w2 = 0; w2 < 6; w2++) s += red[e][w2];
        alpha[e] = (e <= r) ? cdv(r - e) * s : 0.f;
    }
    __syncthreads();
    float s = 0.f;
#pragma unroll
    for (int j = 0; j < ND_; j++) s = fmaf(alpha[j], sE[j][e], s);
    x1[(size_t)bt * D_ + e] = q + 0.5f * s;
}

// ---------------- fused theta QK (via Ktilde) + x4 + LN2 -> y ----------------
#define TC_ 8
__global__ void __launch_bounds__(192) qkfinal_kernel(
    float* __restrict__ y, const float* __restrict__ x3,
    const float* __restrict__ Ktil, const float* __restrict__ Et,
    const float* __restrict__ g2, const float* __restrict__ b2)
{
    __shared__ float sKT[D_][NT_ + 1];   // [e][j]
    __shared__ float red[NT_][6];
    __shared__ float alpha[NT_];
    __shared__ float cdS[NT_];
    __shared__ float lred[2][6];
    int blk = blockIdx.x;
    int b = blk / (T_ / TC_), tc = blk % (T_ / TC_);
    int t0 = tc * TC_;
    int tid = threadIdx.x;
    if (tid < NT_) cdS[tid] = cdv(tid);
    for (int idx = tid; idx < NT_ * D_; idx += 192) {
        int j = idx / D_, e2 = idx % D_;
        sKT[e2][j] = Ktil[(size_t)(b * NT_ + j) * D_ + e2];
    }
    __syncthreads();
    int j = tid & 31, g = tid >> 5;       // 32 j x 6 e-groups
    for (int tt = 0; tt < TC_; tt++) {
        int t = t0 + tt, row = b * T_ + t, r = t >> 3;
        float part = 0.f;
        const float* qr = x3 + (size_t)row * D_;
#pragma unroll
        for (int u = 0; u < 32; u++) {
            int e2 = g * 32 + u;
            part = fmaf(qr[e2], sKT[e2][j], part);
        }
        red[j][g] = part;
        __syncthreads();
        if (tid < NT_) {
            float s = 0.f;
#pragma unroll
            for (int g2i = 0; g2i < 6; g2i++) s += red[tid][g2i];
            alpha[tid] = (tid <= r) ? cdS[r - tid] * s : 0.f;
        }
        __syncthreads();
        int e = tid;
        float s = 0.f;
        for (int jj = 0; jj <= r; jj++)
            s = fmaf(alpha[jj], Et[(size_t)(b * NT_ + jj) * D_ + e], s);
        float x4 = x3[(size_t)row * D_ + e] + 0.5f * s;
        float sm = x4, s2 = x4 * x4;
#pragma unroll
        for (int o = 16; o > 0; o >>= 1) {
            sm += __shfl_xor_sync(~0u, sm, o);
            s2 += __shfl_xor_sync(~0u, s2, o);
        }
        int w = e >> 5, l = e & 31;
        if (l == 0) { lred[0][w] = sm; lred[1][w] = s2; }
        __syncthreads();
        float ts = 0.f, ts2 = 0.f;
#pragma unroll
        for (int i = 0; i < 6; i++) { ts += lred[0][i]; ts2 += lred[1][i]; }
        float m = ts / D_;
        float var = ts2 / D_ - m * m;
        y[(size_t)row * D_ + e] = (x4 - m) * rsqrtf(var + EPS_) * g2[e] + b2[e];
        __syncthreads();
    }
}

// ---------------- LayerNorm over last dim ----------------
__global__ void __launch_bounds__(192) ln_kernel(
    float* __restrict__ out, const float* __restrict__ in,
    const float* __restrict__ g, const float* __restrict__ bta)
{
    int row = blockIdx.x, e = threadIdx.x;
    float v = in[(size_t)row * D_ + e];
    float s = v, s2 = v * v;
#pragma unroll
    for (int o = 16; o > 0; o >>= 1) {
        s  += __shfl_xor_sync(~0u, s,  o);
        s2 += __shfl_xor_sync(~0u, s2, o);
    }
    __shared__ float red[2][6];
    int w = e >> 5, l = e & 31;
    if (l == 0) { red[0][w] = s; red[1][w] = s2; }
    __syncthreads();
    float ts = 0.f, ts2 = 0.f;
#pragma unroll
    for (int i = 0; i < 6; i++) { ts += red[0][i]; ts2 += red[1][i]; }
    float m = ts / D_;
    float var = ts2 / D_ - m * m;
    out[(size_t)row * D_ + e] = (v - m) * rsqrtf(var + EPS_) * g[e] + bta[e];
}

// ---------------- pool over T + classifier ----------------
__global__ void __launch_bounds__(768) poolout_kernel(
    float* __restrict__ out, const float* __restrict__ y,
    const float* __restrict__ Wc, const float* __restrict__ bc)
{
    __shared__ float sp[4][D_];
    __shared__ float pooled[D_];
    int b = blockIdx.x, tid = threadIdx.x;
    int e = tid % D_, tq = tid / D_;
    float s = 0.f;
#pragma unroll 8
    for (int t = tq * 64; t < tq * 64 + 64; t++)
        s += y[(size_t)(b * T_ + t) * D_ + e];
    sp[tq][e] = s;
    __syncthreads();
    if (tid < D_) pooled[tid] = (sp[0][tid] + sp[1][tid] + sp[2][tid] + sp[3][tid]) * (1.f / T_);
    __syncthreads();
    if (tid < NC_) {
        int c = tid;
        float acc = bc[c];
#pragma unroll 8
        for (int e2 = 0; e2 < D_; e2++) acc = fmaf(pooled[e2], Wc[e2 * NC_ + c], acc);
        out[b * NC_ + c] = acc;
    }
}

// =====================================================================
extern "C" void kernel_launch(void* const* d_in, const int* in_sizes, int n_in,
                              void* d_out, int out_size)
{
    const float* x     = (const float*)d_in[0];
    const float* W_in  = (const float*)d_in[1];
    const float* b_in  = (const float*)d_in[2];
    const float* Wv_a  = (const float*)d_in[3];
    const float* bv_a  = (const float*)d_in[4];
    const float* Wo_a  = (const float*)d_in[5];
    const float* bo_a  = (const float*)d_in[6];
    const float* ln1_g = (const float*)d_in[7];
    const float* ln1_b = (const float*)d_in[8];
    const float* pw1_w = (const float*)d_in[9];
    const float* pw1_b = (const float*)d_in[10];
    const float* dw_w  = (const float*)d_in[11];
    const float* dw_b  = (const float*)d_in[12];
    const float* bn_s  = (const float*)d_in[13];
    const float* bn_b  = (const float*)d_in[14];
    const float* pw2_w = (const float*)d_in[15];
    const float* pw2_b = (const float*)d_in[16];
    const float* Wk_t  = (const float*)d_in[17];
    const float* Wv_t  = (const float*)d_in[18];
    const float* Wq_t  = (const float*)d_in[19];
    const float* Wk_d  = (const float*)d_in[20];
    const float* Wv_d  = (const float*)d_in[21];
    const float* Wq_d  = (const float*)d_in[22];
    const float* ln2_g = (const float*)d_in[23];
    const float* ln2_b = (const float*)d_in[24];
    const float* Wc    = (const float*)d_in[25];
    const float* bc    = (const float*)d_in[26];
    float* out = (float*)d_out;

    float *xp, *x1, *x2, *h, *g2, *x3, *y;
    float *Kd, *Vd, *Qd, *Ed, *Kt, *Vt, *Qt, *Et, *Wao, *bao, *Wkqd, *Wkqt;
    cudaGetSymbolAddress((void**)&xp,   g_xp);
    cudaGetSymbolAddress((void**)&x1,   g_x1);
    cudaGetSymbolAddress((void**)&x2,   g_x2);
    cudaGetSymbolAddress((void**)&h,    g_h);
    cudaGetSymbolAddress((void**)&g2,   g_g2);
    cudaGetSymbolAddress((void**)&x3,   g_x3);
    cudaGetSymbolAddress((void**)&y,    g_y);
    cudaGetSymbolAddress((void**)&Kd,   g_Kd);
    cudaGetSymbolAddress((void**)&Vd,   g_Vd);
    cudaGetSymbolAddress((void**)&Qd,   g_Qd);
    cudaGetSymbolAddress((void**)&Ed,   g_Ed);
    cudaGetSymbolAddress((void**)&Kt,   g_Kt);
    cudaGetSymbolAddress((void**)&Vt,   g_Vt);
    cudaGetSymbolAddress((void**)&Qt,   g_Qt);
    cudaGetSymbolAddress((void**)&Et,   g_Et);
    cudaGetSymbolAddress((void**)&Wao,  g_Wao);
    cudaGetSymbolAddress((void**)&bao,  g_bao);
    cudaGetSymbolAddress((void**)&Wkqd, g_Wkqd);
    cudaGetSymbolAddress((void**)&Wkqt, g_Wkqt);

    const int M = B_ * T_;                      // 2048
    dim3 blk256(256);

    // 0) weight prep: Wao, bao, Wkq_d, Wkq_t (one launch, 27+ blocks)
    prep_kernel<<<dim3(3, 4, 3), blk256>>>(Wao, bao, Wkqd, Wkqt,
                                           Wv_a, Wo_a, bv_a, bo_a,
                                           Wk_d, Wq_d, Wk_t, Wq_t);
    // 1) xp = x @ W_in + b_in
    gemm_tiled<<<dim3(D_ / BN, M / BM), blk256>>>(xp, x, W_in, b_in, nullptr, M, D_, MEL_);
    // 2) delta memory: K/V/Ktilde at t in {0,64,128,192}; err recurrence
    projKVQ<<<B_ * ND_, D_>>>(Kd, Vd, Qd, xp, Wk_d, Wv_d, Wkqd, ND_, 64);
    rec_kernel<ND_><<<B_, 256>>>(Ed, Kd, Vd);
    // 3) x1 = xp + 0.5 * delta retrieval (QK via folded keys)
    qkx1_kernel<<<M, D_>>>(x1, xp, Qd, Ed);
    // 4) x2 = x1 + x1@Wao + bao  (folded attention)
    gemm_tiled<<<dim3(D_ / BN, M / BM), blk256>>>(x2, x1, Wao, bao, x1, M, D_, D_);
    // 5) conformer conv module
    ln_kernel<<<M, D_>>>(h, x2, ln1_g, ln1_b);
    gemm_glu<<<dim3(D_ / BN, M / BM), blk256>>>(g2, h, pw1_w, pw1_b, dw_w, dw_b, bn_s, bn_b, M, D_);
    gemm_tiled<<<dim3(D_ / BN, M / BM), blk256>>>(x3, g2, pw2_w, pw2_b, x2, M, D_, D_);
    // 6) theta memory
    projKVQ<<<B_ * NT_, D_>>>(Kt, Vt, Qt, x3, Wk_t, Wv_t, Wkqt, NT_, 8);
    rec_kernel<NT_><<<B_, 256>>>(Et, Kt, Vt);
    // 7) x4 = x3 + 0.5*theta retrieval; LN2 -> y
    qkfinal_kernel<<<B_ * (T_ / TC_), D_>>>(y, x3, Qt, Et, ln2_g, ln2_b);
    // 8) pool + classifier
    poolout_kernel<<<B_, 768>>>(out, y, Wc, bc);
}